// round 13
// baseline (speedup 1.0000x reference)
#include <cuda_runtime.h>
#include <cuda_fp16.h>
#include <cstdint>
#include <cstddef>

#define BATCH 2
#define NSEQ 2048
#define DIM 1024
#define HEADS 16
#define MTOK 4096
#define QKVDIM 3072

// ---------------- device scratch ----------------
__device__ __half g_xh[(size_t)MTOK * DIM];
__device__ __half g_wqh[(size_t)QKVDIM * DIM];
__device__ __half g_woh[(size_t)DIM * DIM];
__device__ __half g_qkv16[(size_t)MTOK * QKVDIM];
__device__ __half g_ath[(size_t)MTOK * DIM];
__device__ int g_ticket;
__device__ int g_qdone[32];      // per (b, qtile) attention-completion counters

// ---------------- helpers ----------------
__device__ __forceinline__ uint32_t smem_u32(const void* p) {
    uint32_t a;
    asm("{ .reg .u64 t; cvta.to.shared.u64 t, %1; cvt.u32.u64 %0, t; }" : "=r"(a) : "l"(p));
    return a;
}
__device__ __forceinline__ void ldsm4(uint32_t* r, uint32_t a) {
    asm volatile("ldmatrix.sync.aligned.m8n8.x4.shared.b16 {%0,%1,%2,%3}, [%4];"
        : "=r"(r[0]), "=r"(r[1]), "=r"(r[2]), "=r"(r[3]) : "r"(a));
}
__device__ __forceinline__ void ldsm4t(uint32_t* r, uint32_t a) {
    asm volatile("ldmatrix.sync.aligned.m8n8.x4.trans.shared.b16 {%0,%1,%2,%3}, [%4];"
        : "=r"(r[0]), "=r"(r[1]), "=r"(r[2]), "=r"(r[3]) : "r"(a));
}
__device__ __forceinline__ void mma16816(float* d, const uint32_t* a, uint32_t b0, uint32_t b1) {
    asm volatile("mma.sync.aligned.m16n8k16.row.col.f32.f16.f16.f32 "
        "{%0,%1,%2,%3},{%4,%5,%6,%7},{%8,%9},{%0,%1,%2,%3};"
        : "+f"(d[0]), "+f"(d[1]), "+f"(d[2]), "+f"(d[3])
        : "r"(a[0]), "r"(a[1]), "r"(a[2]), "r"(a[3]), "r"(b0), "r"(b1));
}
__device__ __forceinline__ void mma16816h(uint32_t* d, const uint32_t* a, uint32_t b0, uint32_t b1) {
    asm volatile("mma.sync.aligned.m16n8k16.row.col.f16.f16.f16.f16 "
        "{%0,%1},{%2,%3,%4,%5},{%6,%7},{%0,%1};"
        : "+r"(d[0]), "+r"(d[1])
        : "r"(a[0]), "r"(a[1]), "r"(a[2]), "r"(a[3]), "r"(b0), "r"(b1));
}
__device__ __forceinline__ void cp16(uint32_t s, const void* g) {
    asm volatile("cp.async.cg.shared.global [%0], [%1], 16;" :: "r"(s), "l"(g));
}
#define CP_COMMIT() asm volatile("cp.async.commit_group;")
#define CP_WAIT(n)  asm volatile("cp.async.wait_group %0;" :: "n"(n))

__device__ __forceinline__ uint32_t packh(float lo, float hi) {
    uint32_t r;
    asm("cvt.rn.f16x2.f32 %0, %1, %2;" : "=r"(r) : "f"(hi), "f"(lo));
    return r;
}
__device__ __forceinline__ float2 unpackh(uint32_t p) {
    float l, h;
    asm("{.reg .b16 a,b; mov.b32 {a,b}, %2; cvt.f32.f16 %0, a; cvt.f32.f16 %1, b;}"
        : "=f"(l), "=f"(h) : "r"(p));
    return make_float2(l, h);
}
__device__ __forceinline__ float fexp64(float s) {  // exp(s/64)
    float t = s * 0.022542120590054683f;
    float k = t + 12582912.0f;
    int ki = __float_as_int(k) << 23;
    float f = t - (k - 12582912.0f);
    float p = 0.0013333558f;
    p = fmaf(p, f, 0.0096181291f);
    p = fmaf(p, f, 0.0555041087f);
    p = fmaf(p, f, 0.2402265070f);
    p = fmaf(p, f, 0.6931471806f);
    p = fmaf(p, f, 1.0f);
    return __int_as_float(__float_as_int(p) + ki);
}

// ---------------- prep ----------------
// RESET=1 variant also resets the job-queue counters (runs before fused kernel).
template <int RESET>
__global__ __launch_bounds__(256) void conv_f16(const float* __restrict__ in,
                                                __half* __restrict__ hi, int n4) {
    if (RESET && blockIdx.x == 0) {
        if (threadIdx.x == 0) g_ticket = 0;
        if (threadIdx.x < 32) g_qdone[threadIdx.x] = 0;
    }
    int i = blockIdx.x * 256 + threadIdx.x;
    if (i >= n4) return;
    float4 v = ((const float4*)in)[i];
    ((uint2*)hi)[i] = make_uint2(packh(v.x, v.y), packh(v.z, v.w));
}

// ---------------- HMMA GEMM body ----------------
#define GSTR 40
#define GMAT (128 * GSTR * 2)         // 10240 B
#define GSTAGE (2 * GMAT)             // 20480 B
#define GSM (3 * GSTAGE)              // 61440 B

__device__ __forceinline__ void gemm_issue(uint32_t sb, int kt,
    const __half* Ah, const __half* Bh, int bm, int bn, int K, int tid)
{
    const int k0 = kt << 5;
    const uint32_t bo = sb + (uint32_t)(kt % 3) * GSTAGE;
#pragma unroll
    for (int m = 0; m < 2; m++) {
        const __half* sp = (m == 0) ? Ah : Bh;
        const int rb = (m == 0) ? bm : bn;
#pragma unroll
        for (int it = 0; it < 2; it++) {
            int id = tid + it * 256;
            int r = id >> 2, ch = id & 3;
            cp16(bo + m * GMAT + r * (GSTR * 2) + ch * 16,
                 sp + (size_t)(rb + r) * K + k0 + ch * 8);
        }
    }
    CP_COMMIT();
}

template <int OUTF32>
__device__ __forceinline__ void gemm_body(uint32_t sb, int bm, int bn,
    const __half* __restrict__ Ah, const __half* __restrict__ Bh,
    const float* __restrict__ bias,
    float* __restrict__ Cf, __half* __restrict__ Ch, int N, int K)
{
    const int tid = threadIdx.x, lane = tid & 31, wid = tid >> 5;
    const int wm = wid >> 2, wn = wid & 3;
    const int KT = K >> 5;

    float acc[4][4][4];
#pragma unroll
    for (int a = 0; a < 4; a++)
#pragma unroll
        for (int b = 0; b < 4; b++)
#pragma unroll
            for (int c = 0; c < 4; c++) acc[a][b][c] = 0.0f;

    gemm_issue(sb, 0, Ah, Bh, bm, bn, K, tid);
    gemm_issue(sb, 1, Ah, Bh, bm, bn, K, tid);

    for (int kt = 0; kt < KT; kt++) {
        if (kt + 1 < KT) { CP_WAIT(1); } else { CP_WAIT(0); }
        __syncthreads();
        const uint32_t bo = sb + (uint32_t)(kt % 3) * GSTAGE;
#pragma unroll
        for (int kk = 0; kk < 2; kk++) {
            const uint32_t cofs = (kk * 16 + ((lane >> 4) << 3)) * 2;
            uint32_t af[4][4];
#pragma unroll
            for (int mt = 0; mt < 4; mt++)
                ldsm4(af[mt], bo + (wm * 64 + mt * 16 + (lane & 15)) * (GSTR * 2) + cofs);
            uint32_t bf[4][2];
#pragma unroll
            for (int g = 0; g < 2; g++) {
                uint32_t t4[4];
                ldsm4(t4, bo + GMAT + (wn * 32 + g * 16 + (lane & 15)) * (GSTR * 2) + cofs);
                bf[2*g][0] = t4[0]; bf[2*g][1] = t4[2];
                bf[2*g+1][0] = t4[1]; bf[2*g+1][1] = t4[3];
            }
#pragma unroll
            for (int mt = 0; mt < 4; mt++)
#pragma unroll
                for (int nf = 0; nf < 4; nf++)
                    mma16816(acc[mt][nf], af[mt], bf[nf][0], bf[nf][1]);
        }
        __syncthreads();
        if (kt + 2 < KT) gemm_issue(sb, kt + 2, Ah, Bh, bm, bn, K, tid);
    }

    const int g = lane >> 2, t = lane & 3;
#pragma unroll
    for (int mt = 0; mt < 4; mt++) {
        int row = bm + wm * 64 + mt * 16 + g;
#pragma unroll
        for (int nf = 0; nf < 4; nf++) {
            int col = bn + wn * 32 + nf * 8 + t * 2;
            if (OUTF32) {
                float bx = bias[col], by = bias[col + 1];
                *(float2*)(Cf + (size_t)row * N + col) =
                    make_float2(acc[mt][nf][0] + bx, acc[mt][nf][1] + by);
                *(float2*)(Cf + (size_t)(row + 8) * N + col) =
                    make_float2(acc[mt][nf][2] + bx, acc[mt][nf][3] + by);
            } else {
                *(uint32_t*)(Ch + (size_t)row * N + col) = packh(acc[mt][nf][0], acc[mt][nf][1]);
                *(uint32_t*)(Ch + (size_t)(row + 8) * N + col) = packh(acc[mt][nf][2], acc[mt][nf][3]);
            }
        }
    }
}

// gemm0: plain kernel (QKV projection, fp16 out)
__global__ __launch_bounds__(256, 2) void gemm0_kernel(
    const __half* __restrict__ Ah, const __half* __restrict__ Bh,
    __half* __restrict__ Ch)
{
    extern __shared__ char smc[];
    gemm_body<0>(smem_u32(smc), blockIdx.y * 128, blockIdx.x * 128,
                 Ah, Bh, nullptr, nullptr, Ch, QKVDIM, DIM);
}

// ---------------- attention job body ----------------
#define ASTR 72
#define A_Q   0
#define A_K(buf)  (128 * ASTR + (buf) * 64 * ASTR)
#define A_V(buf)  (256 * ASTR + (buf) * 64 * ASTR)

__device__ __forceinline__ void attn_body(uint32_t aQ, int qb, int h, int b,
    const __half* __restrict__ qkv, __half* __restrict__ oh)
{
    const int tid = threadIdx.x, lane = tid & 31, wid = tid >> 5;
    const __half* qbase = qkv + ((size_t)b * NSEQ + qb) * QKVDIM + h * 64;
    const __half* kvb = qkv + ((size_t)b * NSEQ) * QKVDIM + DIM + h * 64;

#pragma unroll
    for (int it = 0; it < 4; it++) {
        int id = tid + it * 256;
        int r = id >> 3, ch = id & 7;
        cp16(aQ + (A_Q + r * ASTR + ch * 8) * 2, qbase + (size_t)r * QKVDIM + ch * 8);
    }
    CP_COMMIT();
#pragma unroll
    for (int it = 0; it < 2; it++) {
        int id = tid + it * 256;
        int r = id >> 3, ch = id & 7;
        cp16(aQ + (A_K(0) + r * ASTR + ch * 8) * 2, kvb + (size_t)r * QKVDIM + ch * 8);
        cp16(aQ + (A_V(0) + r * ASTR + ch * 8) * 2, kvb + DIM + (size_t)r * QKVDIM + ch * 8);
    }
    CP_COMMIT();

    CP_WAIT(1);
    __syncthreads();
    uint32_t qf[4][4];
#pragma unroll
    for (int kq = 0; kq < 4; kq++)
        ldsm4(qf[kq], aQ + ((wid * 16 + (lane & 15)) * ASTR + kq * 16 + ((lane >> 4) << 3)) * 2);

    float of[8][4];
#pragma unroll
    for (int i = 0; i < 8; i++)
#pragma unroll
        for (int j = 0; j < 4; j++) of[i][j] = 0.0f;
    float l0 = 0.0f, l1 = 0.0f;

    for (int kt = 0; kt < NSEQ / 64; kt++) {
        const int buf = kt & 1;
        if (kt + 1 < NSEQ / 64) {
            const __half* nb = kvb + (size_t)(kt + 1) * 64 * QKVDIM;
#pragma unroll
            for (int it = 0; it < 2; it++) {
                int id = tid + it * 256;
                int r = id >> 3, ch = id & 7;
                cp16(aQ + (A_K(buf ^ 1) + r * ASTR + ch * 8) * 2, nb + (size_t)r * QKVDIM + ch * 8);
                cp16(aQ + (A_V(buf ^ 1) + r * ASTR + ch * 8) * 2, nb + DIM + (size_t)r * QKVDIM + ch * 8);
            }
            CP_COMMIT();
            CP_WAIT(1);
        } else {
            CP_WAIT(0);
        }
        __syncthreads();
        const uint32_t aK = aQ + A_K(buf) * 2, aV = aQ + A_V(buf) * 2;

        uint32_t sfh[8][2];
#pragma unroll
        for (int i = 0; i < 8; i++) { sfh[i][0] = 0u; sfh[i][1] = 0u; }
#pragma unroll
        for (int kq = 0; kq < 4; kq++) {
            uint32_t kf[8][2];
#pragma unroll
            for (int g = 0; g < 4; g++) {
                uint32_t t4[4];
                ldsm4(t4, aK + ((g * 16 + (lane & 15)) * ASTR + kq * 16 + ((lane >> 4) << 3)) * 2);
                kf[2*g][0] = t4[0]; kf[2*g][1] = t4[2];
                kf[2*g+1][0] = t4[1]; kf[2*g+1][1] = t4[3];
            }
#pragma unroll
            for (int nf = 0; nf < 8; nf++)
                mma16816h(sfh[nf], qf[kq], kf[nf][0], kf[nf][1]);
        }

        uint32_t ph[8][2];
#pragma unroll
        for (int nf = 0; nf < 8; nf++) {
            float2 s01 = unpackh(sfh[nf][0]);
            float2 s23 = unpackh(sfh[nf][1]);
            float p0 = fexp64(s01.x), p1 = fexp64(s01.y);
            float p2 = fexp64(s23.x), p3 = fexp64(s23.y);
            l0 += p0 + p1; l1 += p2 + p3;
            ph[nf][0] = packh(p0, p1);
            ph[nf][1] = packh(p2, p3);
        }

#pragma unroll
        for (int kk = 0; kk < 4; kk++) {
            uint32_t pa[4] = {ph[2*kk][0], ph[2*kk][1], ph[2*kk+1][0], ph[2*kk+1][1]};
#pragma unroll
            for (int g = 0; g < 4; g++) {
                uint32_t t4[4];
                ldsm4t(t4, aV + ((kk * 16 + (lane & 15)) * ASTR + g * 16 + ((lane >> 4) << 3)) * 2);
                mma16816(of[2*g],     pa, t4[0], t4[1]);
                mma16816(of[2*g + 1], pa, t4[2], t4[3]);
            }
        }
        __syncthreads();
    }

    l0 += __shfl_xor_sync(0xffffffffu, l0, 1);
    l0 += __shfl_xor_sync(0xffffffffu, l0, 2);
    l1 += __shfl_xor_sync(0xffffffffu, l1, 1);
    l1 += __shfl_xor_sync(0xffffffffu, l1, 2);
    float i0 = 1.0f / l0, i1 = 1.0f / l1;

    const int g = lane >> 2, t = lane & 3;
    const int tok = qb + wid * 16 + g;
#pragma unroll
    for (int nf = 0; nf < 8; nf++) {
        int col = h * 64 + nf * 8 + t * 2;
        size_t idx0 = ((size_t)b * NSEQ + tok) * DIM + col;
        size_t idx1 = ((size_t)b * NSEQ + tok + 8) * DIM + col;
        *(uint32_t*)&oh[idx0] = packh(of[nf][0] * i0, of[nf][1] * i0);
        *(uint32_t*)&oh[idx1] = packh(of[nf][2] * i1, of[nf][3] * i1);
    }
}

// ---------------- fused persistent kernel ----------------
// Attention tickets 0..511 GROUP-MAJOR: group = t>>4 = b*16+qt, h = t&15.
// All 16 heads of a group are consecutive -> early groups complete in wave 1,
// so wave-2 slack slots can run their out-proj tiles.
#define N_ATTN 512
#define N_TOTAL 768

__global__ __launch_bounds__(256, 2) void fused_attn_proj(
    const __half* __restrict__ qkv, __half* __restrict__ ath,
    const __half* __restrict__ woh, const float* __restrict__ bias,
    float* __restrict__ out)
{
    extern __shared__ char smc[];
    __shared__ int s_ticket;
    const uint32_t sb = smem_u32(smc);

    for (;;) {
        if (threadIdx.x == 0) s_ticket = atomicAdd(&g_ticket, 1);
        __syncthreads();
        const int t = s_ticket;
        if (t >= N_TOTAL) break;

        if (t < N_ATTN) {
            // attention job: group-major ordering
            const int group = t >> 4, h = t & 15;
            const int b = group >> 4, qt = group & 15;
            attn_body(sb, qt << 7, h, b, qkv, ath);
            __threadfence();
            __syncthreads();
            if (threadIdx.x == 0) atomicAdd(&g_qdone[group], 1);
        } else {
            // out-projection tile: g1 = 0..255; group = g1>>3 (row block), n-tile = g1&7
            const int g1 = t - N_ATTN;
            const int group = g1 >> 3;
            const int bm = group * 128, bn = (g1 & 7) * 128;
            if (threadIdx.x == 0) {
                while (atomicAdd(&g_qdone[group], 0) < 16) __nanosleep(200);
            }
            __syncthreads();
            gemm_body<1>(sb, bm, bn, ath, woh, bias, out, nullptr, DIM, DIM);
        }
        __syncthreads();
    }
}

// ---------------- launch ----------------
extern "C" void kernel_launch(void* const* d_in, const int* in_sizes, int n_in,
                              void* d_out, int out_size)
{
    const float* x = (const float*)d_in[0];
    const float* w_qkv = (const float*)d_in[1];
    const float* w_out = (const float*)d_in[2];
    const float* b_out = (const float*)d_in[3];
    float* out = (float*)d_out;

    __half *xh, *wqh, *woh, *qkv16, *ath;
    cudaGetSymbolAddress((void**)&xh, g_xh);
    cudaGetSymbolAddress((void**)&wqh, g_wqh);
    cudaGetSymbolAddress((void**)&woh, g_woh);
    cudaGetSymbolAddress((void**)&qkv16, g_qkv16);
    cudaGetSymbolAddress((void**)&ath, g_ath);

    conv_f16<1><<<(MTOK * DIM / 4 + 255) / 256, 256>>>(x, xh, MTOK * DIM / 4);
    conv_f16<0><<<(QKVDIM * DIM / 4 + 255) / 256, 256>>>(w_qkv, wqh, QKVDIM * DIM / 4);
    conv_f16<0><<<(DIM * DIM / 4 + 255) / 256, 256>>>(w_out, woh, DIM * DIM / 4);

    cudaFuncSetAttribute((const void*)gemm0_kernel, cudaFuncAttributeMaxDynamicSharedMemorySize, GSM);
    cudaFuncSetAttribute((const void*)fused_attn_proj, cudaFuncAttributeMaxDynamicSharedMemorySize, GSM);

    // QKV projection (single fp16 term), fp16 out
    {
        dim3 grid(QKVDIM / 128, MTOK / 128);
        gemm0_kernel<<<grid, 256, GSM>>>(xh, wqh, qkv16);
    }
    // fused persistent attention + out-projection
    {
        fused_attn_proj<<<296, 256, GSM>>>(qkv16, ath, woh, b_out, out);
    }
}

// round 14
// speedup vs baseline: 1.0725x; 1.0725x over previous
#include <cuda_runtime.h>
#include <cuda_fp16.h>
#include <cstdint>
#include <cstddef>

#define BATCH 2
#define NSEQ 2048
#define DIM 1024
#define HEADS 16
#define MTOK 4096
#define QKVDIM 3072

// ---------------- device scratch ----------------
__device__ __half g_xh[(size_t)MTOK * DIM];
__device__ __half g_wqh[(size_t)QKVDIM * DIM];
__device__ __half g_woh[(size_t)DIM * DIM];
__device__ __half g_qkv16[(size_t)MTOK * QKVDIM];
__device__ __half g_ath[(size_t)MTOK * DIM];

// ---------------- helpers ----------------
__device__ __forceinline__ uint32_t smem_u32(const void* p) {
    uint32_t a;
    asm("{ .reg .u64 t; cvta.to.shared.u64 t, %1; cvt.u32.u64 %0, t; }" : "=r"(a) : "l"(p));
    return a;
}
__device__ __forceinline__ void ldsm4(uint32_t* r, uint32_t a) {
    asm volatile("ldmatrix.sync.aligned.m8n8.x4.shared.b16 {%0,%1,%2,%3}, [%4];"
        : "=r"(r[0]), "=r"(r[1]), "=r"(r[2]), "=r"(r[3]) : "r"(a));
}
__device__ __forceinline__ void ldsm4t(uint32_t* r, uint32_t a) {
    asm volatile("ldmatrix.sync.aligned.m8n8.x4.trans.shared.b16 {%0,%1,%2,%3}, [%4];"
        : "=r"(r[0]), "=r"(r[1]), "=r"(r[2]), "=r"(r[3]) : "r"(a));
}
__device__ __forceinline__ void mma16816(float* d, const uint32_t* a, uint32_t b0, uint32_t b1) {
    asm volatile("mma.sync.aligned.m16n8k16.row.col.f32.f16.f16.f32 "
        "{%0,%1,%2,%3},{%4,%5,%6,%7},{%8,%9},{%0,%1,%2,%3};"
        : "+f"(d[0]), "+f"(d[1]), "+f"(d[2]), "+f"(d[3])
        : "r"(a[0]), "r"(a[1]), "r"(a[2]), "r"(a[3]), "r"(b0), "r"(b1));
}
__device__ __forceinline__ void mma16816h(uint32_t* d, const uint32_t* a, uint32_t b0, uint32_t b1) {
    asm volatile("mma.sync.aligned.m16n8k16.row.col.f16.f16.f16.f16 "
        "{%0,%1},{%2,%3,%4,%5},{%6,%7},{%0,%1};"
        : "+r"(d[0]), "+r"(d[1])
        : "r"(a[0]), "r"(a[1]), "r"(a[2]), "r"(a[3]), "r"(b0), "r"(b1));
}
__device__ __forceinline__ void cp16(uint32_t s, const void* g) {
    asm volatile("cp.async.cg.shared.global [%0], [%1], 16;" :: "r"(s), "l"(g));
}
#define CP_COMMIT() asm volatile("cp.async.commit_group;")
#define CP_WAIT(n)  asm volatile("cp.async.wait_group %0;" :: "n"(n))

__device__ __forceinline__ uint32_t packh(float lo, float hi) {
    uint32_t r;
    asm("cvt.rn.f16x2.f32 %0, %1, %2;" : "=r"(r) : "f"(hi), "f"(lo));
    return r;
}
__device__ __forceinline__ float2 unpackh(uint32_t p) {
    float l, h;
    asm("{.reg .b16 a,b; mov.b32 {a,b}, %2; cvt.f32.f16 %0, a; cvt.f32.f16 %1, b;}"
        : "=f"(l), "=f"(h) : "r"(p));
    return make_float2(l, h);
}
__device__ __forceinline__ float fexp64(float s) {  // exp(s/64)
    float t = s * 0.022542120590054683f;
    float k = t + 12582912.0f;
    int ki = __float_as_int(k) << 23;
    float f = t - (k - 12582912.0f);
    float p = 0.0013333558f;
    p = fmaf(p, f, 0.0096181291f);
    p = fmaf(p, f, 0.0555041087f);
    p = fmaf(p, f, 0.2402265070f);
    p = fmaf(p, f, 0.6931471806f);
    p = fmaf(p, f, 1.0f);
    return __int_as_float(__float_as_int(p) + ki);
}

// ---------------- prep: one merged fp32 -> fp16 convert over all three tensors ----------------
#define CN0 (MTOK * DIM / 4)       // x:      1048576 float4s
#define CN1 (QKVDIM * DIM / 4)     // w_qkv:   786432
#define CN2 (DIM * DIM / 4)        // w_out:   262144
#define CNT (CN0 + CN1 + CN2)

__global__ __launch_bounds__(256) void conv3_f16(
    const float* __restrict__ x, const float* __restrict__ wq, const float* __restrict__ wo,
    __half* __restrict__ xh, __half* __restrict__ wqh, __half* __restrict__ woh)
{
    int i = blockIdx.x * 256 + threadIdx.x;
    const float* in;
    __half* out;
    if (i < CN0)            { in = x;  out = xh; }
    else if (i < CN0 + CN1) { i -= CN0; in = wq; out = wqh; }
    else if (i < CNT)       { i -= CN0 + CN1; in = wo; out = woh; }
    else return;
    float4 v = ((const float4*)in)[i];
    ((uint2*)out)[i] = make_uint2(packh(v.x, v.y), packh(v.z, v.w));
}

// ---------------- HMMA GEMM body ----------------
#define GSTR 40
#define GMAT (128 * GSTR * 2)         // 10240 B
#define GSTAGE (2 * GMAT)             // 20480 B
#define GSM (3 * GSTAGE)              // 61440 B

__device__ __forceinline__ void gemm_issue(uint32_t sb, int kt,
    const __half* Ah, const __half* Bh, int bm, int bn, int K, int tid)
{
    const int k0 = kt << 5;
    const uint32_t bo = sb + (uint32_t)(kt % 3) * GSTAGE;
#pragma unroll
    for (int m = 0; m < 2; m++) {
        const __half* sp = (m == 0) ? Ah : Bh;
        const int rb = (m == 0) ? bm : bn;
#pragma unroll
        for (int it = 0; it < 2; it++) {
            int id = tid + it * 256;
            int r = id >> 2, ch = id & 3;
            cp16(bo + m * GMAT + r * (GSTR * 2) + ch * 16,
                 sp + (size_t)(rb + r) * K + k0 + ch * 8);
        }
    }
    CP_COMMIT();
}

template <int OUTF32>
__device__ __forceinline__ void gemm_body(uint32_t sb, int bm, int bn,
    const __half* __restrict__ Ah, const __half* __restrict__ Bh,
    const float* __restrict__ bias,
    float* __restrict__ Cf, __half* __restrict__ Ch, int N, int K)
{
    const int tid = threadIdx.x, lane = tid & 31, wid = tid >> 5;
    const int wm = wid >> 2, wn = wid & 3;
    const int KT = K >> 5;

    float acc[4][4][4];
#pragma unroll
    for (int a = 0; a < 4; a++)
#pragma unroll
        for (int b = 0; b < 4; b++)
#pragma unroll
            for (int c = 0; c < 4; c++) acc[a][b][c] = 0.0f;

    gemm_issue(sb, 0, Ah, Bh, bm, bn, K, tid);
    gemm_issue(sb, 1, Ah, Bh, bm, bn, K, tid);

    for (int kt = 0; kt < KT; kt++) {
        if (kt + 1 < KT) { CP_WAIT(1); } else { CP_WAIT(0); }
        __syncthreads();
        const uint32_t bo = sb + (uint32_t)(kt % 3) * GSTAGE;
#pragma unroll
        for (int kk = 0; kk < 2; kk++) {
            const uint32_t cofs = (kk * 16 + ((lane >> 4) << 3)) * 2;
            uint32_t af[4][4];
#pragma unroll
            for (int mt = 0; mt < 4; mt++)
                ldsm4(af[mt], bo + (wm * 64 + mt * 16 + (lane & 15)) * (GSTR * 2) + cofs);
            uint32_t bf[4][2];
#pragma unroll
            for (int g = 0; g < 2; g++) {
                uint32_t t4[4];
                ldsm4(t4, bo + GMAT + (wn * 32 + g * 16 + (lane & 15)) * (GSTR * 2) + cofs);
                bf[2*g][0] = t4[0]; bf[2*g][1] = t4[2];
                bf[2*g+1][0] = t4[1]; bf[2*g+1][1] = t4[3];
            }
#pragma unroll
            for (int mt = 0; mt < 4; mt++)
#pragma unroll
                for (int nf = 0; nf < 4; nf++)
                    mma16816(acc[mt][nf], af[mt], bf[nf][0], bf[nf][1]);
        }
        __syncthreads();
        if (kt + 2 < KT) gemm_issue(sb, kt + 2, Ah, Bh, bm, bn, K, tid);
    }

    const int g = lane >> 2, t = lane & 3;
#pragma unroll
    for (int mt = 0; mt < 4; mt++) {
        int row = bm + wm * 64 + mt * 16 + g;
#pragma unroll
        for (int nf = 0; nf < 4; nf++) {
            int col = bn + wn * 32 + nf * 8 + t * 2;
            if (OUTF32) {
                float bx = bias[col], by = bias[col + 1];
                *(float2*)(Cf + (size_t)row * N + col) =
                    make_float2(acc[mt][nf][0] + bx, acc[mt][nf][1] + by);
                *(float2*)(Cf + (size_t)(row + 8) * N + col) =
                    make_float2(acc[mt][nf][2] + bx, acc[mt][nf][3] + by);
            } else {
                *(uint32_t*)(Ch + (size_t)row * N + col) = packh(acc[mt][nf][0], acc[mt][nf][1]);
                *(uint32_t*)(Ch + (size_t)(row + 8) * N + col) = packh(acc[mt][nf][2], acc[mt][nf][3]);
            }
        }
    }
}

// gemm0: QKV projection, fp16 out
__global__ __launch_bounds__(256, 2) void gemm0_kernel(
    const __half* __restrict__ Ah, const __half* __restrict__ Bh,
    __half* __restrict__ Ch)
{
    extern __shared__ char smc[];
    gemm_body<0>(smem_u32(smc), blockIdx.y * 128, blockIdx.x * 128,
                 Ah, Bh, nullptr, nullptr, Ch, QKVDIM, DIM);
}

// gemm1: output projection + bias, fp32 out
__global__ __launch_bounds__(256, 2) void gemm1_kernel(
    const __half* __restrict__ Ah, const __half* __restrict__ Bh,
    const float* __restrict__ bias, float* __restrict__ Cf)
{
    extern __shared__ char smc[];
    gemm_body<1>(smem_u32(smc), blockIdx.y * 128, blockIdx.x * 128,
                 Ah, Bh, bias, Cf, nullptr, DIM, DIM);
}

// ---------------- attention: fp16 in/out, fp16-acc S, fp32-acc PV ----------------
#define ASTR 72
#define A_Q   0
#define A_K(buf)  (128 * ASTR + (buf) * 64 * ASTR)
#define A_V(buf)  (256 * ASTR + (buf) * 64 * ASTR)
#define A_SMEM (384 * ASTR * 2)   // 55296 B

__global__ __launch_bounds__(256, 2) void attn_kernel(const __half* __restrict__ qkv,
                                                      __half* __restrict__ oh)
{
    extern __shared__ __half sA[];
    const uint32_t aQ = smem_u32(sA);

    const int tid = threadIdx.x, lane = tid & 31, wid = tid >> 5;
    const int qb = blockIdx.x * 128, h = blockIdx.y, b = blockIdx.z;
    const __half* qbase = qkv + ((size_t)b * NSEQ + qb) * QKVDIM + h * 64;
    const __half* kvb = qkv + ((size_t)b * NSEQ) * QKVDIM + DIM + h * 64;

#pragma unroll
    for (int it = 0; it < 4; it++) {
        int id = tid + it * 256;
        int r = id >> 3, ch = id & 7;
        cp16(aQ + (A_Q + r * ASTR + ch * 8) * 2, qbase + (size_t)r * QKVDIM + ch * 8);
    }
    CP_COMMIT();
#pragma unroll
    for (int it = 0; it < 2; it++) {
        int id = tid + it * 256;
        int r = id >> 3, ch = id & 7;
        cp16(aQ + (A_K(0) + r * ASTR + ch * 8) * 2, kvb + (size_t)r * QKVDIM + ch * 8);
        cp16(aQ + (A_V(0) + r * ASTR + ch * 8) * 2, kvb + DIM + (size_t)r * QKVDIM + ch * 8);
    }
    CP_COMMIT();

    CP_WAIT(1);
    __syncthreads();
    uint32_t qf[4][4];
#pragma unroll
    for (int kq = 0; kq < 4; kq++)
        ldsm4(qf[kq], aQ + ((wid * 16 + (lane & 15)) * ASTR + kq * 16 + ((lane >> 4) << 3)) * 2);

    float of[8][4];
#pragma unroll
    for (int i = 0; i < 8; i++)
#pragma unroll
        for (int j = 0; j < 4; j++) of[i][j] = 0.0f;
    float l0 = 0.0f, l1 = 0.0f;

    for (int kt = 0; kt < NSEQ / 64; kt++) {
        const int buf = kt & 1;
        if (kt + 1 < NSEQ / 64) {
            const __half* nb = kvb + (size_t)(kt + 1) * 64 * QKVDIM;
#pragma unroll
            for (int it = 0; it < 2; it++) {
                int id = tid + it * 256;
                int r = id >> 3, ch = id & 7;
                cp16(aQ + (A_K(buf ^ 1) + r * ASTR + ch * 8) * 2, nb + (size_t)r * QKVDIM + ch * 8);
                cp16(aQ + (A_V(buf ^ 1) + r * ASTR + ch * 8) * 2, nb + DIM + (size_t)r * QKVDIM + ch * 8);
            }
            CP_COMMIT();
            CP_WAIT(1);
        } else {
            CP_WAIT(0);
        }
        __syncthreads();
        const uint32_t aK = aQ + A_K(buf) * 2, aV = aQ + A_V(buf) * 2;

        uint32_t sfh[8][2];
#pragma unroll
        for (int i = 0; i < 8; i++) { sfh[i][0] = 0u; sfh[i][1] = 0u; }
#pragma unroll
        for (int kq = 0; kq < 4; kq++) {
            uint32_t kf[8][2];
#pragma unroll
            for (int g = 0; g < 4; g++) {
                uint32_t t4[4];
                ldsm4(t4, aK + ((g * 16 + (lane & 15)) * ASTR + kq * 16 + ((lane >> 4) << 3)) * 2);
                kf[2*g][0] = t4[0]; kf[2*g][1] = t4[2];
                kf[2*g+1][0] = t4[1]; kf[2*g+1][1] = t4[3];
            }
#pragma unroll
            for (int nf = 0; nf < 8; nf++)
                mma16816h(sfh[nf], qf[kq], kf[nf][0], kf[nf][1]);
        }

        uint32_t ph[8][2];
#pragma unroll
        for (int nf = 0; nf < 8; nf++) {
            float2 s01 = unpackh(sfh[nf][0]);
            float2 s23 = unpackh(sfh[nf][1]);
            float p0 = fexp64(s01.x), p1 = fexp64(s01.y);
            float p2 = fexp64(s23.x), p3 = fexp64(s23.y);
            l0 += p0 + p1; l1 += p2 + p3;
            ph[nf][0] = packh(p0, p1);
            ph[nf][1] = packh(p2, p3);
        }

#pragma unroll
        for (int kk = 0; kk < 4; kk++) {
            uint32_t pa[4] = {ph[2*kk][0], ph[2*kk][1], ph[2*kk+1][0], ph[2*kk+1][1]};
#pragma unroll
            for (int g = 0; g < 4; g++) {
                uint32_t t4[4];
                ldsm4t(t4, aV + ((kk * 16 + (lane & 15)) * ASTR + g * 16 + ((lane >> 4) << 3)) * 2);
                mma16816(of[2*g],     pa, t4[0], t4[1]);
                mma16816(of[2*g + 1], pa, t4[2], t4[3]);
            }
        }
        __syncthreads();
    }

    l0 += __shfl_xor_sync(0xffffffffu, l0, 1);
    l0 += __shfl_xor_sync(0xffffffffu, l0, 2);
    l1 += __shfl_xor_sync(0xffffffffu, l1, 1);
    l1 += __shfl_xor_sync(0xffffffffu, l1, 2);
    float i0 = 1.0f / l0, i1 = 1.0f / l1;

    const int g = lane >> 2, t = lane & 3;
    const int tok = qb + wid * 16 + g;
#pragma unroll
    for (int nf = 0; nf < 8; nf++) {
        int col = h * 64 + nf * 8 + t * 2;
        size_t idx0 = ((size_t)b * NSEQ + tok) * DIM + col;
        size_t idx1 = ((size_t)b * NSEQ + tok + 8) * DIM + col;
        *(uint32_t*)&oh[idx0] = packh(of[nf][0] * i0, of[nf][1] * i0);
        *(uint32_t*)&oh[idx1] = packh(of[nf][2] * i1, of[nf][3] * i1);
    }
}

// ---------------- launch ----------------
extern "C" void kernel_launch(void* const* d_in, const int* in_sizes, int n_in,
                              void* d_out, int out_size)
{
    const float* x = (const float*)d_in[0];
    const float* w_qkv = (const float*)d_in[1];
    const float* w_out = (const float*)d_in[2];
    const float* b_out = (const float*)d_in[3];
    float* out = (float*)d_out;

    __half *xh, *wqh, *woh, *qkv16, *ath;
    cudaGetSymbolAddress((void**)&xh, g_xh);
    cudaGetSymbolAddress((void**)&wqh, g_wqh);
    cudaGetSymbolAddress((void**)&woh, g_woh);
    cudaGetSymbolAddress((void**)&qkv16, g_qkv16);
    cudaGetSymbolAddress((void**)&ath, g_ath);

    // one merged prep launch
    conv3_f16<<<(CNT + 255) / 256, 256>>>(x, w_qkv, w_out, xh, wqh, woh);

    cudaFuncSetAttribute((const void*)gemm0_kernel, cudaFuncAttributeMaxDynamicSharedMemorySize, GSM);
    cudaFuncSetAttribute((const void*)gemm1_kernel, cudaFuncAttributeMaxDynamicSharedMemorySize, GSM);
    cudaFuncSetAttribute((const void*)attn_kernel, cudaFuncAttributeMaxDynamicSharedMemorySize, A_SMEM);

    // QKV projection, fp16 out (one merged launch)
    {
        dim3 grid(QKVDIM / 128, MTOK / 128);
        gemm0_kernel<<<grid, 256, GSM>>>(xh, wqh, qkv16);
    }
    // attention, fp16 out
    {
        dim3 grid(NSEQ / 128, HEADS, BATCH);
        attn_kernel<<<grid, 256, A_SMEM>>>(qkv16, ath);
    }
    // output projection + bias, fp32 out
    {
        dim3 grid(DIM / 128, MTOK / 128);
        gemm1_kernel<<<grid, 256, GSM>>>(ath, woh, b_out, out);
    }
}

// round 16
// speedup vs baseline: 1.2099x; 1.1282x over previous
#include <cuda_runtime.h>
#include <cuda_fp16.h>
#include <cstdint>
#include <cstddef>

#define BATCH 2
#define NSEQ 2048
#define DIM 1024
#define HEADS 16
#define MTOK 4096
#define QKVDIM 3072

// ---------------- device scratch ----------------
__device__ __half g_xh[(size_t)MTOK * DIM];
__device__ __half g_wqh[(size_t)QKVDIM * DIM];
__device__ __half g_woh[(size_t)DIM * DIM];
__device__ __half g_qkv16[(size_t)MTOK * QKVDIM];
__device__ __half g_ath[(size_t)MTOK * DIM];

// ---------------- helpers ----------------
__device__ __forceinline__ uint32_t smem_u32(const void* p) {
    uint32_t a;
    asm("{ .reg .u64 t; cvta.to.shared.u64 t, %1; cvt.u32.u64 %0, t; }" : "=r"(a) : "l"(p));
    return a;
}
__device__ __forceinline__ void ldsm4(uint32_t* r, uint32_t a) {
    asm volatile("ldmatrix.sync.aligned.m8n8.x4.shared.b16 {%0,%1,%2,%3}, [%4];"
        : "=r"(r[0]), "=r"(r[1]), "=r"(r[2]), "=r"(r[3]) : "r"(a));
}
__device__ __forceinline__ void ldsm4t(uint32_t* r, uint32_t a) {
    asm volatile("ldmatrix.sync.aligned.m8n8.x4.trans.shared.b16 {%0,%1,%2,%3}, [%4];"
        : "=r"(r[0]), "=r"(r[1]), "=r"(r[2]), "=r"(r[3]) : "r"(a));
}
__device__ __forceinline__ void mma16816(float* d, const uint32_t* a, uint32_t b0, uint32_t b1) {
    asm volatile("mma.sync.aligned.m16n8k16.row.col.f32.f16.f16.f32 "
        "{%0,%1,%2,%3},{%4,%5,%6,%7},{%8,%9},{%0,%1,%2,%3};"
        : "+f"(d[0]), "+f"(d[1]), "+f"(d[2]), "+f"(d[3])
        : "r"(a[0]), "r"(a[1]), "r"(a[2]), "r"(a[3]), "r"(b0), "r"(b1));
}
__device__ __forceinline__ void mma16816h(uint32_t* d, const uint32_t* a, uint32_t b0, uint32_t b1) {
    asm volatile("mma.sync.aligned.m16n8k16.row.col.f16.f16.f16.f16 "
        "{%0,%1},{%2,%3,%4,%5},{%6,%7},{%0,%1};"
        : "+r"(d[0]), "+r"(d[1])
        : "r"(a[0]), "r"(a[1]), "r"(a[2]), "r"(a[3]), "r"(b0), "r"(b1));
}
__device__ __forceinline__ void cp16(uint32_t s, const void* g) {
    asm volatile("cp.async.cg.shared.global [%0], [%1], 16;" :: "r"(s), "l"(g));
}
#define CP_COMMIT() asm volatile("cp.async.commit_group;")
#define CP_WAIT(n)  asm volatile("cp.async.wait_group %0;" :: "n"(n))

__device__ __forceinline__ uint32_t packh(float lo, float hi) {
    uint32_t r;
    asm("cvt.rn.f16x2.f32 %0, %1, %2;" : "=r"(r) : "f"(hi), "f"(lo));
    return r;
}
__device__ __forceinline__ float2 unpackh(uint32_t p) {
    float l, h;
    asm("{.reg .b16 a,b; mov.b32 {a,b}, %2; cvt.f32.f16 %0, a; cvt.f32.f16 %1, b;}"
        : "=f"(l), "=f"(h) : "r"(p));
    return make_float2(l, h);
}
__device__ __forceinline__ float fexp64(float s) {  // exp(s/64)
    float t = s * 0.022542120590054683f;
    float k = t + 12582912.0f;
    int ki = __float_as_int(k) << 23;
    float f = t - (k - 12582912.0f);
    float p = 0.0013333558f;
    p = fmaf(p, f, 0.0096181291f);
    p = fmaf(p, f, 0.0555041087f);
    p = fmaf(p, f, 0.2402265070f);
    p = fmaf(p, f, 0.6931471806f);
    p = fmaf(p, f, 1.0f);
    return __int_as_float(__float_as_int(p) + ki);
}

// ---------------- prep: one merged fp32 -> fp16 convert over all three tensors ----------------
#define CN0 (MTOK * DIM / 4)
#define CN1 (QKVDIM * DIM / 4)
#define CN2 (DIM * DIM / 4)
#define CNT (CN0 + CN1 + CN2)

__global__ __launch_bounds__(256) void conv3_f16(
    const float* __restrict__ x, const float* __restrict__ wq, const float* __restrict__ wo,
    __half* __restrict__ xh, __half* __restrict__ wqh, __half* __restrict__ woh)
{
    int i = blockIdx.x * 256 + threadIdx.x;
    const float* in;
    __half* out;
    if (i < CN0)            { in = x;  out = xh; }
    else if (i < CN0 + CN1) { i -= CN0; in = wq; out = wqh; }
    else if (i < CNT)       { i -= CN0 + CN1; in = wo; out = woh; }
    else return;
    float4 v = ((const float4*)in)[i];
    ((uint2*)out)[i] = make_uint2(packh(v.x, v.y), packh(v.z, v.w));
}

// ---------------- HMMA GEMM body ----------------
#define GSTR 40
#define GMAT (128 * GSTR * 2)         // 10240 B
#define GSTAGE (2 * GMAT)             // 20480 B
#define GSM (3 * GSTAGE)              // 61440 B

__device__ __forceinline__ void gemm_issue(uint32_t sb, int kt,
    const __half* Ah, const __half* Bh, int bm, int bn, int K, int tid)
{
    const int k0 = kt << 5;
    const uint32_t bo = sb + (uint32_t)(kt % 3) * GSTAGE;
#pragma unroll
    for (int m = 0; m < 2; m++) {
        const __half* sp = (m == 0) ? Ah : Bh;
        const int rb = (m == 0) ? bm : bn;
#pragma unroll
        for (int it = 0; it < 2; it++) {
            int id = tid + it * 256;
            int r = id >> 2, ch = id & 3;
            cp16(bo + m * GMAT + r * (GSTR * 2) + ch * 16,
                 sp + (size_t)(rb + r) * K + k0 + ch * 8);
        }
    }
    CP_COMMIT();
}

template <int OUTF32>
__device__ __forceinline__ void gemm_body(uint32_t sb, int bm, int bn,
    const __half* __restrict__ Ah, const __half* __restrict__ Bh,
    const float* __restrict__ bias,
    float* __restrict__ Cf, __half* __restrict__ Ch, int N, int K)
{
    const int tid = threadIdx.x, lane = tid & 31, wid = tid >> 5;
    const int wm = wid >> 2, wn = wid & 3;
    const int KT = K >> 5;

    float acc[4][4][4];
#pragma unroll
    for (int a = 0; a < 4; a++)
#pragma unroll
        for (int b = 0; b < 4; b++)
#pragma unroll
            for (int c = 0; c < 4; c++) acc[a][b][c] = 0.0f;

    gemm_issue(sb, 0, Ah, Bh, bm, bn, K, tid);
    gemm_issue(sb, 1, Ah, Bh, bm, bn, K, tid);

    for (int kt = 0; kt < KT; kt++) {
        if (kt + 1 < KT) { CP_WAIT(1); } else { CP_WAIT(0); }
        __syncthreads();
        const uint32_t bo = sb + (uint32_t)(kt % 3) * GSTAGE;
#pragma unroll
        for (int kk = 0; kk < 2; kk++) {
            const uint32_t cofs = (kk * 16 + ((lane >> 4) << 3)) * 2;
            uint32_t af[4][4];
#pragma unroll
            for (int mt = 0; mt < 4; mt++)
                ldsm4(af[mt], bo + (wm * 64 + mt * 16 + (lane & 15)) * (GSTR * 2) + cofs);
            uint32_t bf[4][2];
#pragma unroll
            for (int g = 0; g < 2; g++) {
                uint32_t t4[4];
                ldsm4(t4, bo + GMAT + (wn * 32 + g * 16 + (lane & 15)) * (GSTR * 2) + cofs);
                bf[2*g][0] = t4[0]; bf[2*g][1] = t4[2];
                bf[2*g+1][0] = t4[1]; bf[2*g+1][1] = t4[3];
            }
#pragma unroll
            for (int mt = 0; mt < 4; mt++)
#pragma unroll
                for (int nf = 0; nf < 4; nf++)
                    mma16816(acc[mt][nf], af[mt], bf[nf][0], bf[nf][1]);
        }
        __syncthreads();
        if (kt + 2 < KT) gemm_issue(sb, kt + 2, Ah, Bh, bm, bn, K, tid);
    }

    const int g = lane >> 2, t = lane & 3;
#pragma unroll
    for (int mt = 0; mt < 4; mt++) {
        int row = bm + wm * 64 + mt * 16 + g;
#pragma unroll
        for (int nf = 0; nf < 4; nf++) {
            int col = bn + wn * 32 + nf * 8 + t * 2;
            if (OUTF32) {
                float bx = bias[col], by = bias[col + 1];
                *(float2*)(Cf + (size_t)row * N + col) =
                    make_float2(acc[mt][nf][0] + bx, acc[mt][nf][1] + by);
                *(float2*)(Cf + (size_t)(row + 8) * N + col) =
                    make_float2(acc[mt][nf][2] + bx, acc[mt][nf][3] + by);
            } else {
                *(uint32_t*)(Ch + (size_t)row * N + col) = packh(acc[mt][nf][0], acc[mt][nf][1]);
                *(uint32_t*)(Ch + (size_t)(row + 8) * N + col) = packh(acc[mt][nf][2], acc[mt][nf][3]);
            }
        }
    }
}

// gemm0: QKV projection slice (rows [rbase, rbase+2048)), fp16 out
__global__ __launch_bounds__(256, 2) void gemm0_kernel(
    const __half* __restrict__ Ah, const __half* __restrict__ Bh,
    __half* __restrict__ Ch, int rbase)
{
    extern __shared__ char smc[];
    gemm_body<0>(smem_u32(smc), rbase + blockIdx.y * 128, blockIdx.x * 128,
                 Ah, Bh, nullptr, nullptr, Ch, QKVDIM, DIM);
}

// gemm1: output projection slice + bias, fp32 out
__global__ __launch_bounds__(256, 2) void gemm1_kernel(
    const __half* __restrict__ Ah, const __half* __restrict__ Bh,
    const float* __restrict__ bias, float* __restrict__ Cf, int rbase)
{
    extern __shared__ char smc[];
    gemm_body<1>(smem_u32(smc), rbase + blockIdx.y * 128, blockIdx.x * 128,
                 Ah, Bh, bias, Cf, nullptr, DIM, DIM);
}

// ---------------- attention: one batch per launch ----------------
#define ASTR 72
#define A_Q   0
#define A_K(buf)  (128 * ASTR + (buf) * 64 * ASTR)
#define A_V(buf)  (256 * ASTR + (buf) * 64 * ASTR)
#define A_SMEM (384 * ASTR * 2)   // 55296 B

__global__ __launch_bounds__(256, 2) void attn_kernel(const __half* __restrict__ qkv,
                                                      __half* __restrict__ oh, int b)
{
    extern __shared__ __half sA[];
    const uint32_t aQ = smem_u32(sA);

    const int tid = threadIdx.x, lane = tid & 31, wid = tid >> 5;
    const int qb = blockIdx.x * 128, h = blockIdx.y;
    const __half* qbase = qkv + ((size_t)b * NSEQ + qb) * QKVDIM + h * 64;
    const __half* kvb = qkv + ((size_t)b * NSEQ) * QKVDIM + DIM + h * 64;

#pragma unroll
    for (int it = 0; it < 4; it++) {
        int id = tid + it * 256;
        int r = id >> 3, ch = id & 7;
        cp16(aQ + (A_Q + r * ASTR + ch * 8) * 2, qbase + (size_t)r * QKVDIM + ch * 8);
    }
    CP_COMMIT();
#pragma unroll
    for (int it = 0; it < 2; it++) {
        int id = tid + it * 256;
        int r = id >> 3, ch = id & 7;
        cp16(aQ + (A_K(0) + r * ASTR + ch * 8) * 2, kvb + (size_t)r * QKVDIM + ch * 8);
        cp16(aQ + (A_V(0) + r * ASTR + ch * 8) * 2, kvb + DIM + (size_t)r * QKVDIM + ch * 8);
    }
    CP_COMMIT();

    CP_WAIT(1);
    __syncthreads();
    uint32_t qf[4][4];
#pragma unroll
    for (int kq = 0; kq < 4; kq++)
        ldsm4(qf[kq], aQ + ((wid * 16 + (lane & 15)) * ASTR + kq * 16 + ((lane >> 4) << 3)) * 2);

    float of[8][4];
#pragma unroll
    for (int i = 0; i < 8; i++)
#pragma unroll
        for (int j = 0; j < 4; j++) of[i][j] = 0.0f;
    float l0 = 0.0f, l1 = 0.0f;

    for (int kt = 0; kt < NSEQ / 64; kt++) {
        const int buf = kt & 1;
        if (kt + 1 < NSEQ / 64) {
            const __half* nb = kvb + (size_t)(kt + 1) * 64 * QKVDIM;
#pragma unroll
            for (int it = 0; it < 2; it++) {
                int id = tid + it * 256;
                int r = id >> 3, ch = id & 7;
                cp16(aQ + (A_K(buf ^ 1) + r * ASTR + ch * 8) * 2, nb + (size_t)r * QKVDIM + ch * 8);
                cp16(aQ + (A_V(buf ^ 1) + r * ASTR + ch * 8) * 2, nb + DIM + (size_t)r * QKVDIM + ch * 8);
            }
            CP_COMMIT();
            CP_WAIT(1);
        } else {
            CP_WAIT(0);
        }
        __syncthreads();
        const uint32_t aK = aQ + A_K(buf) * 2, aV = aQ + A_V(buf) * 2;

        uint32_t sfh[8][2];
#pragma unroll
        for (int i = 0; i < 8; i++) { sfh[i][0] = 0u; sfh[i][1] = 0u; }
#pragma unroll
        for (int kq = 0; kq < 4; kq++) {
            uint32_t kf[8][2];
#pragma unroll
            for (int g = 0; g < 4; g++) {
                uint32_t t4[4];
                ldsm4(t4, aK + ((g * 16 + (lane & 15)) * ASTR + kq * 16 + ((lane >> 4) << 3)) * 2);
                kf[2*g][0] = t4[0]; kf[2*g][1] = t4[2];
                kf[2*g+1][0] = t4[1]; kf[2*g+1][1] = t4[3];
            }
#pragma unroll
            for (int nf = 0; nf < 8; nf++)
                mma16816h(sfh[nf], qf[kq], kf[nf][0], kf[nf][1]);
        }

        uint32_t ph[8][2];
#pragma unroll
        for (int nf = 0; nf < 8; nf++) {
            float2 s01 = unpackh(sfh[nf][0]);
            float2 s23 = unpackh(sfh[nf][1]);
            float p0 = fexp64(s01.x), p1 = fexp64(s01.y);
            float p2 = fexp64(s23.x), p3 = fexp64(s23.y);
            l0 += p0 + p1; l1 += p2 + p3;
            ph[nf][0] = packh(p0, p1);
            ph[nf][1] = packh(p2, p3);
        }

#pragma unroll
        for (int kk = 0; kk < 4; kk++) {
            uint32_t pa[4] = {ph[2*kk][0], ph[2*kk][1], ph[2*kk+1][0], ph[2*kk+1][1]};
#pragma unroll
            for (int g = 0; g < 4; g++) {
                uint32_t t4[4];
                ldsm4t(t4, aV + ((kk * 16 + (lane & 15)) * ASTR + g * 16 + ((lane >> 4) << 3)) * 2);
                mma16816(of[2*g],     pa, t4[0], t4[1]);
                mma16816(of[2*g + 1], pa, t4[2], t4[3]);
            }
        }
        __syncthreads();
    }

    l0 += __shfl_xor_sync(0xffffffffu, l0, 1);
    l0 += __shfl_xor_sync(0xffffffffu, l0, 2);
    l1 += __shfl_xor_sync(0xffffffffu, l1, 1);
    l1 += __shfl_xor_sync(0xffffffffu, l1, 2);
    float i0 = 1.0f / l0, i1 = 1.0f / l1;

    const int g = lane >> 2, t = lane & 3;
    const int tok = qb + wid * 16 + g;
#pragma unroll
    for (int nf = 0; nf < 8; nf++) {
        int col = h * 64 + nf * 8 + t * 2;
        size_t idx0 = ((size_t)b * NSEQ + tok) * DIM + col;
        size_t idx1 = ((size_t)b * NSEQ + tok + 8) * DIM + col;
        *(uint32_t*)&oh[idx0] = packh(of[nf][0] * i0, of[nf][1] * i0);
        *(uint32_t*)&oh[idx1] = packh(of[nf][2] * i1, of[nf][3] * i1);
    }
}

// ---------------- launch: two-stream batch pipeline ----------------
// Stream/events are created ONCE on the first call (the non-captured
// correctness run); captured replays reuse the handles so no resource
// creation happens inside graph capture. Work is identical on every call.
extern "C" void kernel_launch(void* const* d_in, const int* in_sizes, int n_in,
                              void* d_out, int out_size)
{
    const float* x = (const float*)d_in[0];
    const float* w_qkv = (const float*)d_in[1];
    const float* w_out = (const float*)d_in[2];
    const float* b_out = (const float*)d_in[3];
    float* out = (float*)d_out;

    __half *xh, *wqh, *woh, *qkv16, *ath;
    cudaGetSymbolAddress((void**)&xh, g_xh);
    cudaGetSymbolAddress((void**)&wqh, g_wqh);
    cudaGetSymbolAddress((void**)&woh, g_woh);
    cudaGetSymbolAddress((void**)&qkv16, g_qkv16);
    cudaGetSymbolAddress((void**)&ath, g_ath);

    static cudaStream_t s1 = nullptr;
    static cudaEvent_t eFork = nullptr, eJoin = nullptr;
    static bool attrs_set = false;
    if (s1 == nullptr) {
        cudaStreamCreateWithFlags(&s1, cudaStreamNonBlocking);
        cudaEventCreateWithFlags(&eFork, cudaEventDisableTiming);
        cudaEventCreateWithFlags(&eJoin, cudaEventDisableTiming);
    }
    if (!attrs_set) {
        cudaFuncSetAttribute((const void*)gemm0_kernel, cudaFuncAttributeMaxDynamicSharedMemorySize, GSM);
        cudaFuncSetAttribute((const void*)gemm1_kernel, cudaFuncAttributeMaxDynamicSharedMemorySize, GSM);
        cudaFuncSetAttribute((const void*)attn_kernel, cudaFuncAttributeMaxDynamicSharedMemorySize, A_SMEM);
        attrs_set = true;
    }

    // prep on main stream
    conv3_f16<<<(CNT + 255) / 256, 256>>>(x, w_qkv, w_out, xh, wqh, woh);
    cudaEventRecord(eFork, 0);
    cudaStreamWaitEvent(s1, eFork, 0);

    // batch-0 chain on main stream
    {
        dim3 g0(QKVDIM / 128, NSEQ / 128);
        gemm0_kernel<<<g0, 256, GSM, 0>>>(xh, wqh, qkv16, 0);
        dim3 ga(NSEQ / 128, HEADS);
        attn_kernel<<<ga, 256, A_SMEM, 0>>>(qkv16, ath, 0);
        dim3 g1(DIM / 128, NSEQ / 128);
        gemm1_kernel<<<g1, 256, GSM, 0>>>(ath, woh, b_out, out, 0);
    }
    // batch-1 chain on s1
    {
        dim3 g0(QKVDIM / 128, NSEQ / 128);
        gemm0_kernel<<<g0, 256, GSM, s1>>>(xh, wqh, qkv16, NSEQ);
        dim3 ga(NSEQ / 128, HEADS);
        attn_kernel<<<ga, 256, A_SMEM, s1>>>(qkv16, ath, 1);
        dim3 g1(DIM / 128, NSEQ / 128);
        gemm1_kernel<<<g1, 256, GSM, s1>>>(ath, woh, b_out, out, NSEQ);
    }

    cudaEventRecord(eJoin, s1);
    cudaStreamWaitEvent(0, eJoin, 0);
}